// round 5
// baseline (speedup 1.0000x reference)
#include <cuda_runtime.h>
#include <cstdint>

#define KK 16
#define BB 512
#define NP 4096
#define EPSF 1e-13f
#define TOLF 1.001e-5f   // np.isclose to 1.0: rtol(1e-5)*1.0 + atol(1e-8)

// packed labels: byte k of element n = c_in[n][k] (all < 32)
__device__ uint4 g_c8[NP];

__global__ void pack_labels_kernel(const int* __restrict__ c_in) {
    int t = blockIdx.x * blockDim.x + threadIdx.x;
    if (t < NP) {
        const int4* p = (const int4*)(c_in + t * KK);
        int4 a = p[0], b = p[1], c = p[2], d = p[3];
        uint4 r;
        r.x = (a.x & 255u) | ((a.y & 255u) << 8) | ((a.z & 255u) << 16) | ((a.w & 255u) << 24);
        r.y = (b.x & 255u) | ((b.y & 255u) << 8) | ((b.z & 255u) << 16) | ((b.w & 255u) << 24);
        r.z = (c.x & 255u) | ((c.y & 255u) << 8) | ((c.z & 255u) << 16) | ((c.w & 255u) << 24);
        r.w = (d.x & 255u) | ((d.y & 255u) << 8) | ((d.z & 255u) << 16) | ((d.w & 255u) << 24);
        g_c8[t] = r;
    }
}

__global__ __launch_bounds__(512, 3) void beran_kernel(
    const float* __restrict__ delta,
    const float* __restrict__ c_p,
    const float* __restrict__ bwp,
    float* __restrict__ out)
{
    __shared__ float w_sh[512 * 9];     // padded rows of 8 (+1), 18 KB, conflict-free
    __shared__ float s_score[KK * 32];  // 2 KB
    __shared__ float ws1[16];
    __shared__ float ws2[16];
    __shared__ float s_tot_sh, g2_sh;

    const int tid  = threadIdx.x;
    const int lane = tid & 31;
    const int wid  = tid >> 5;          // 0..15
    const int b    = blockIdx.x;
    const unsigned FULL = 0xFFFFFFFFu;

    // ---- Phase A: softmax + score table. warp wid handles concept k=wid ----
    {
        float x = c_p[(wid * BB + b) * 32 + lane];
        float m = x;
        #pragma unroll
        for (int d = 16; d; d >>= 1) m = fmaxf(m, __shfl_xor_sync(FULL, m, d));
        float e = __expf(x - m);
        float s = e;
        #pragma unroll
        for (int d = 16; d; d >>= 1) s += __shfl_xor_sync(FULL, s, d);
        float p = __fdividef(e, s);
        float ssq = p * p;
        #pragma unroll
        for (int d = 16; d; d >>= 1) ssq += __shfl_xor_sync(FULL, ssq, d);
        s_score[wid * 32 + lane] = ssq - 2.0f * p + 1.0f;   // score[k][v]
    }
    __syncthreads();

    float sreg[KK];
    #pragma unroll
    for (int k = 0; k < KK; k++) sreg[k] = s_score[k * 32 + lane];

    const float bw  = fminf(fmaxf(bwp[0], 0.1f), 10.0f);
    const float nib = -1.0f / bw;

    // ---- Phase B: coalesced gather, tree-sum, padded transpose store ----
    // n = (wid*8+ci)*32 + lane; store addr = (n>>3)*9 + (n&7)
    const int wpart = (lane >> 3) * 9 + (lane & 7);
    #pragma unroll
    for (int ci = 0; ci < 8; ci++) {
        uint4 pk = g_c8[(wid * 8 + ci) * 32 + lane];
        // tree-sum: pairwise to shorten the dependent-add chain
        float a0 = __shfl_sync(FULL, sreg[0],  (int)pk.x)
                 + __shfl_sync(FULL, sreg[1],  (int)(pk.x >> 8));
        float a1 = __shfl_sync(FULL, sreg[2],  (int)(pk.x >> 16))
                 + __shfl_sync(FULL, sreg[3],  (int)(pk.x >> 24));
        float a2 = __shfl_sync(FULL, sreg[4],  (int)pk.y)
                 + __shfl_sync(FULL, sreg[5],  (int)(pk.y >> 8));
        float a3 = __shfl_sync(FULL, sreg[6],  (int)(pk.y >> 16))
                 + __shfl_sync(FULL, sreg[7],  (int)(pk.y >> 24));
        float a4 = __shfl_sync(FULL, sreg[8],  (int)pk.z)
                 + __shfl_sync(FULL, sreg[9],  (int)(pk.z >> 8));
        float a5 = __shfl_sync(FULL, sreg[10], (int)(pk.z >> 16))
                 + __shfl_sync(FULL, sreg[11], (int)(pk.z >> 24));
        float a6 = __shfl_sync(FULL, sreg[12], (int)pk.w)
                 + __shfl_sync(FULL, sreg[13], (int)(pk.w >> 8));
        float a7 = __shfl_sync(FULL, sreg[14], (int)(pk.w >> 16))
                 + __shfl_sync(FULL, sreg[15], (int)(pk.w >> 24));
        float m = ((a0 + a1) + (a2 + a3)) + ((a4 + a5) + (a6 + a7));
        w_sh[(wid * 8 + ci) * 36 + wpart] = __expf(m * nib);
    }
    __syncthreads();

    // ---- Phase C: scan #1 over w. thread owns n = 8*tid .. 8*tid+7 ----
    float o[8];
    {
        const int rbase = tid * 9;
        #pragma unroll
        for (int j = 0; j < 8; j++) o[j] = w_sh[rbase + j];
    }
    // load delta early to overlap
    float dl[8];
    {
        const float4* dp = (const float4*)(delta + tid * 8);
        float4 d0 = dp[0], d1 = dp[1];
        dl[0] = d0.x; dl[1] = d0.y; dl[2] = d0.z; dl[3] = d0.w;
        dl[4] = d1.x; dl[5] = d1.y; dl[6] = d1.z; dl[7] = d1.w;
    }

    float cw[8];
    cw[0] = o[0];
    #pragma unroll
    for (int j = 1; j < 8; j++) cw[j] = cw[j - 1] + o[j];

    float tot = cw[7];
    float ti = tot;
    #pragma unroll
    for (int d = 1; d < 32; d <<= 1) {
        float u = __shfl_up_sync(FULL, ti, d);
        if (lane >= d) ti += u;
    }
    if (lane == 31) ws1[wid] = ti;
    __syncthreads();
    if (wid == 0) {
        float v = (lane < 16) ? ws1[lane] : 0.0f;
        float vi = v;
        #pragma unroll
        for (int d = 1; d < 16; d <<= 1) {
            float u = __shfl_up_sync(FULL, vi, d);
            if (lane >= d) vi += u;
        }
        if (lane < 16) ws1[lane] = vi - v;   // exclusive warp-prefix
        if (lane == 15) s_tot_sh = vi;       // grand total s
    }
    __syncthreads();

    const float off1  = ws1[wid] + (ti - tot);   // exclusive prefix
    const float s_tot = s_tot_sh;
    // |1 - cum/s| <= TOL  <=>  |s - cum| <= TOL*s (unnormalized guard)
    const float tols = (s_tot < EPSF) ? 3.0e38f : TOLF * s_tot;

    // ---- Phase D: xi = log(t_prev/t) on unnormalized residuals ----
    float t_[9];
    t_[0] = s_tot - off1;
    #pragma unroll
    for (int j = 0; j < 8; j++) t_[j + 1] = s_tot - (off1 + cw[j]);

    float hz[8];
    float tot2 = 0.0f;
    #pragma unroll
    for (int j = 0; j < 8; j++) {
        float tp = t_[j], t = t_[j + 1];
        bool bad = (fabsf(t) <= tols) || (fabsf(tp) <= tols);
        float xi = bad ? 0.0f : __logf(__fdividef(tp, t));
        float v = dl[j] * xi;
        tot2 += v;
        hz[j] = v;
    }
    #pragma unroll
    for (int j = 1; j < 8; j++) hz[j] += hz[j - 1];

    // ---- Phase E: scan #2 (hazards) ----
    float ti2 = tot2;
    #pragma unroll
    for (int d = 1; d < 32; d <<= 1) {
        float u = __shfl_up_sync(FULL, ti2, d);
        if (lane >= d) ti2 += u;
    }
    if (lane == 31) ws2[wid] = ti2;
    __syncthreads();
    if (wid == 0) {
        float v = (lane < 16) ? ws2[lane] : 0.0f;
        float vi = v;
        #pragma unroll
        for (int d = 1; d < 16; d <<= 1) {
            float u = __shfl_up_sync(FULL, vi, d);
            if (lane >= d) vi += u;
        }
        if (lane < 16) ws2[lane] = vi - v;
        if (lane == 15) g2_sh = vi;          // grand total hazards
    }
    __syncthreads();
    const float off2 = ws2[wid] + (ti2 - tot2);

    // s2 telescopes: sum(surv_steps) = 1 - surv[N-1]
    const float s2   = 1.0f - __expf(-g2_sh);
    const float inv2 = (s2 < EPSF) ? 0.0f : 1.0f / s2;
    float prev = (tid == 0) ? 1.0f : __expf(-off2);   // surv[base-1]

    // ---- Phase F: surv + steps ----
    float surv[8];
    #pragma unroll
    for (int j = 0; j < 8; j++) surv[j] = __expf(-(hz[j] + off2));

    {
        float4* op = (float4*)(out + (size_t)b * NP + tid * 8);
        op[0] = make_float4(surv[0], surv[1], surv[2], surv[3]);
        op[1] = make_float4(surv[4], surv[5], surv[6], surv[7]);
    }
    float st[8];
    #pragma unroll
    for (int j = 0; j < 8; j++) {
        st[j] = (prev - surv[j]) * inv2;
        prev = surv[j];
    }
    {
        float4* op = (float4*)(out + (size_t)BB * NP + (size_t)b * NP + tid * 8);
        op[0] = make_float4(st[0], st[1], st[2], st[3]);
        op[1] = make_float4(st[4], st[5], st[6], st[7]);
    }
}

extern "C" void kernel_launch(void* const* d_in, const int* in_sizes, int n_in,
                              void* d_out, int out_size) {
    const int*   c_in  = (const int*)d_in[0];
    const float* delta = (const float*)d_in[1];
    const float* c_p   = (const float*)d_in[2];
    const float* bwp   = (const float*)d_in[3];
    float* out = (float*)d_out;

    pack_labels_kernel<<<16, 256>>>(c_in);
    beran_kernel<<<BB, 512>>>(delta, c_p, bwp, out);
}

// round 6
// speedup vs baseline: 1.1252x; 1.1252x over previous
#include <cuda_runtime.h>
#include <cstdint>

#define KK 16
#define BB 512
#define NP 4096
#define EPSF 1e-13f
#define TOLF 1.001e-5f   // np.isclose to 1.0: rtol(1e-5)*1.0 + atol(1e-8)

// transposed packed labels: pk for train point n lives at g_c8T[(n&7)*512 + (n>>3)]
// so beran thread t (owning n = 8t..8t+7) reads g_c8T[j*512 + t] -> coalesced.
__device__ uint4 g_c8T[NP];

__global__ void pack_labels_kernel(const int* __restrict__ c_in) {
    int t = blockIdx.x * blockDim.x + threadIdx.x;
    if (t < NP) {
        const int4* p = (const int4*)(c_in + t * KK);
        int4 a = p[0], b = p[1], c = p[2], d = p[3];
        uint4 r;
        r.x = (a.x & 255u) | ((a.y & 255u) << 8) | ((a.z & 255u) << 16) | ((a.w & 255u) << 24);
        r.y = (b.x & 255u) | ((b.y & 255u) << 8) | ((b.z & 255u) << 16) | ((b.w & 255u) << 24);
        r.z = (c.x & 255u) | ((c.y & 255u) << 8) | ((c.z & 255u) << 16) | ((c.w & 255u) << 24);
        r.w = (d.x & 255u) | ((d.y & 255u) << 8) | ((d.z & 255u) << 16) | ((d.w & 255u) << 24);
        g_c8T[(t & 7) * 512 + (t >> 3)] = r;
    }
}

__global__ __launch_bounds__(512, 3) void beran_kernel(
    const float* __restrict__ delta,
    const float* __restrict__ c_p,
    const float* __restrict__ bwp,
    float* __restrict__ out)
{
    __shared__ float s_score[KK * 32];  // 2 KB
    __shared__ float ws1[16];
    __shared__ float ws2[16];
    __shared__ float s_tot_sh, g2_sh;

    const int tid  = threadIdx.x;
    const int lane = tid & 31;
    const int wid  = tid >> 5;          // 0..15
    const int b    = blockIdx.x;
    const unsigned FULL = 0xFFFFFFFFu;

    // ---- Phase A: softmax + score table. warp wid handles concept k=wid ----
    {
        float x = c_p[(wid * BB + b) * 32 + lane];
        float m = x;
        #pragma unroll
        for (int d = 16; d; d >>= 1) m = fmaxf(m, __shfl_xor_sync(FULL, m, d));
        float e = __expf(x - m);
        float s = e;
        #pragma unroll
        for (int d = 16; d; d >>= 1) s += __shfl_xor_sync(FULL, s, d);
        float p = __fdividef(e, s);
        float ssq = p * p;
        #pragma unroll
        for (int d = 16; d; d >>= 1) ssq += __shfl_xor_sync(FULL, ssq, d);
        s_score[wid * 32 + lane] = ssq - 2.0f * p + 1.0f;   // score[k][v]
    }
    __syncthreads();

    float sreg[KK];
    #pragma unroll
    for (int k = 0; k < KK; k++) sreg[k] = s_score[k * 32 + lane];

    const float bw  = fminf(fmaxf(bwp[0], 0.1f), 10.0f);
    const float nib = -1.0f / bw;

    // ---- Phase B: gather straight into scan registers (coalesced g_c8T) ----
    float o[8];
    #pragma unroll
    for (int j = 0; j < 8; j++) {
        uint4 pk = g_c8T[j * 512 + tid];
        float m = 0.0f;
        // labels < 32; shfl.idx uses b[4:0] only -> no masks
        m += __shfl_sync(FULL, sreg[0],  (int)pk.x);
        m += __shfl_sync(FULL, sreg[1],  (int)(pk.x >> 8));
        m += __shfl_sync(FULL, sreg[2],  (int)(pk.x >> 16));
        m += __shfl_sync(FULL, sreg[3],  (int)(pk.x >> 24));
        m += __shfl_sync(FULL, sreg[4],  (int)pk.y);
        m += __shfl_sync(FULL, sreg[5],  (int)(pk.y >> 8));
        m += __shfl_sync(FULL, sreg[6],  (int)(pk.y >> 16));
        m += __shfl_sync(FULL, sreg[7],  (int)(pk.y >> 24));
        m += __shfl_sync(FULL, sreg[8],  (int)pk.z);
        m += __shfl_sync(FULL, sreg[9],  (int)(pk.z >> 8));
        m += __shfl_sync(FULL, sreg[10], (int)(pk.z >> 16));
        m += __shfl_sync(FULL, sreg[11], (int)(pk.z >> 24));
        m += __shfl_sync(FULL, sreg[12], (int)pk.w);
        m += __shfl_sync(FULL, sreg[13], (int)(pk.w >> 8));
        m += __shfl_sync(FULL, sreg[14], (int)(pk.w >> 16));
        m += __shfl_sync(FULL, sreg[15], (int)(pk.w >> 24));
        o[j] = __expf(m * nib);
    }

    // ---- Phase C: scan #1 over w ----
    float cw[8];
    cw[0] = o[0];
    #pragma unroll
    for (int j = 1; j < 8; j++) cw[j] = cw[j - 1] + o[j];

    float tot = cw[7];
    float ti = tot;
    #pragma unroll
    for (int d = 1; d < 32; d <<= 1) {
        float u = __shfl_up_sync(FULL, ti, d);
        if (lane >= d) ti += u;
    }
    if (lane == 31) ws1[wid] = ti;
    __syncthreads();
    if (wid == 0) {
        float v = (lane < 16) ? ws1[lane] : 0.0f;
        float vi = v;
        #pragma unroll
        for (int d = 1; d < 16; d <<= 1) {
            float u = __shfl_up_sync(FULL, vi, d);
            if (lane >= d) vi += u;
        }
        if (lane < 16) ws1[lane] = vi - v;   // exclusive warp-prefix
        if (lane == 15) s_tot_sh = vi;       // grand total s
    }
    __syncthreads();

    const float off1  = ws1[wid] + (ti - tot);
    const float s_tot = s_tot_sh;
    const float tols  = (s_tot < EPSF) ? 3.0e38f : TOLF * s_tot;  // unnormalized guard

    // delta load (overlaps with scan latency)
    float dl[8];
    {
        const float4* dp = (const float4*)(delta + tid * 8);
        float4 d0 = dp[0], d1 = dp[1];
        dl[0] = d0.x; dl[1] = d0.y; dl[2] = d0.z; dl[3] = d0.w;
        dl[4] = d1.x; dl[5] = d1.y; dl[6] = d1.z; dl[7] = d1.w;
    }

    // ---- Phase D: xi = log(t_prev/t) on unnormalized residuals ----
    float hz[8];
    float tot2 = 0.0f;
    {
        float tprev = s_tot - off1;
        #pragma unroll
        for (int j = 0; j < 8; j++) {
            float t = s_tot - (off1 + cw[j]);
            bool bad = (fabsf(t) <= tols) || (fabsf(tprev) <= tols);
            float xi = bad ? 0.0f : __logf(__fdividef(tprev, t));
            float v = dl[j] * xi;
            tot2 += v;
            hz[j] = v;
            tprev = t;
        }
    }
    #pragma unroll
    for (int j = 1; j < 8; j++) hz[j] += hz[j - 1];

    // ---- Phase E: scan #2 (hazards) ----
    float ti2 = tot2;
    #pragma unroll
    for (int d = 1; d < 32; d <<= 1) {
        float u = __shfl_up_sync(FULL, ti2, d);
        if (lane >= d) ti2 += u;
    }
    if (lane == 31) ws2[wid] = ti2;
    __syncthreads();
    if (wid == 0) {
        float v = (lane < 16) ? ws2[lane] : 0.0f;
        float vi = v;
        #pragma unroll
        for (int d = 1; d < 16; d <<= 1) {
            float u = __shfl_up_sync(FULL, vi, d);
            if (lane >= d) vi += u;
        }
        if (lane < 16) ws2[lane] = vi - v;
        if (lane == 15) g2_sh = vi;          // grand total hazards
    }
    __syncthreads();
    const float off2 = ws2[wid] + (ti2 - tot2);

    // s2 telescopes: sum(surv_steps) = 1 - surv[N-1]
    const float s2   = 1.0f - __expf(-g2_sh);
    const float inv2 = (s2 < EPSF) ? 0.0f : 1.0f / s2;
    float prev = (tid == 0) ? 1.0f : __expf(-off2);   // surv[8*tid - 1]

    // ---- Phase F: surv + steps ----
    float surv[8];
    #pragma unroll
    for (int j = 0; j < 8; j++) surv[j] = __expf(-(hz[j] + off2));

    {
        float4* op = (float4*)(out + (size_t)b * NP + tid * 8);
        op[0] = make_float4(surv[0], surv[1], surv[2], surv[3]);
        op[1] = make_float4(surv[4], surv[5], surv[6], surv[7]);
    }
    float st[8];
    #pragma unroll
    for (int j = 0; j < 8; j++) {
        st[j] = (prev - surv[j]) * inv2;
        prev = surv[j];
    }
    {
        float4* op = (float4*)(out + (size_t)BB * NP + (size_t)b * NP + tid * 8);
        op[0] = make_float4(st[0], st[1], st[2], st[3]);
        op[1] = make_float4(st[4], st[5], st[6], st[7]);
    }
}

extern "C" void kernel_launch(void* const* d_in, const int* in_sizes, int n_in,
                              void* d_out, int out_size) {
    const int*   c_in  = (const int*)d_in[0];
    const float* delta = (const float*)d_in[1];
    const float* c_p   = (const float*)d_in[2];
    const float* bwp   = (const float*)d_in[3];
    float* out = (float*)d_out;

    pack_labels_kernel<<<16, 256>>>(c_in);
    beran_kernel<<<BB, 512>>>(delta, c_p, bwp, out);
}